// round 1
// baseline (speedup 1.0000x reference)
#include <cuda_runtime.h>

// Rotation by 15 deg, bilinear, border constant 0.
// Input:  (32, 3, 512, 512) fp32
// Output: (32, 3, 512, 512) fp32
//
// dst(y,x) = bilinear_src( R(-15deg) @ (x-256, y-256) + (256,256) )
// Coordinates are identical for all 96 (B*C) planes, so one thread computes
// the taps once and sweeps all planes for max MLP + amortized ALU.

#define H 512
#define W 512
#define HW (H * W)
#define NPLANES 96   // 32 * 3

// fp32-rounded cos/sin of 15 degrees (matches jnp.cos/sin of fp32 theta to ~1e-8)
#define COS_A 0.96592582628906829f
#define SIN_A 0.25881904510252074f

__global__ __launch_bounds__(256)
void rotation_kernel(const float* __restrict__ in, float* __restrict__ out) {
    int idx = blockIdx.x * blockDim.x + threadIdx.x;
    if (idx >= HW) return;

    int x = idx & (W - 1);
    int y = idx >> 9;

    float xf = (float)x - 256.0f;
    float yf = (float)y - 256.0f;

    // xs = a*(x-cx) - b*(y-cy) + cx ; ys = b*(x-cx) + a*(y-cy) + cy
    float xs = COS_A * xf - SIN_A * yf + 256.0f;
    float ys = SIN_A * xf + COS_A * yf + 256.0f;

    float x0f = floorf(xs);
    float y0f = floorf(ys);
    float wx = xs - x0f;
    float wy = ys - y0f;

    int x0 = (int)x0f;
    int y0 = (int)y0f;
    int x1 = x0 + 1;
    int y1 = y0 + 1;

    bool vx0 = (x0 >= 0) && (x0 <= W - 1);
    bool vx1 = (x1 >= 0) && (x1 <= W - 1);
    bool vy0 = (y0 >= 0) && (y0 <= H - 1);
    bool vy1 = (y1 >= 0) && (y1 <= H - 1);

    // weights with validity folded in (invalid tap contributes 0, like the ref)
    float w00 = (1.0f - wy) * (1.0f - wx) * (float)(vy0 && vx0);
    float w01 = (1.0f - wy) * wx          * (float)(vy0 && vx1);
    float w10 = wy          * (1.0f - wx) * (float)(vy1 && vx0);
    float w11 = wy          * wx          * (float)(vy1 && vx1);

    int xc0 = min(max(x0, 0), W - 1);
    int xc1 = min(max(x1, 0), W - 1);
    int yc0 = min(max(y0, 0), H - 1);
    int yc1 = min(max(y1, 0), H - 1);

    int o00 = yc0 * W + xc0;
    int o01 = yc0 * W + xc1;
    int o10 = yc1 * W + xc0;
    int o11 = yc1 * W + xc1;

    const float* p = in;
    float* q = out + idx;

    #pragma unroll 4
    for (int bc = 0; bc < NPLANES; bc++) {
        float v = w00 * __ldg(p + o00)
                + w01 * __ldg(p + o01)
                + w10 * __ldg(p + o10)
                + w11 * __ldg(p + o11);
        q[(long)bc * HW] = v;
        p += HW;
    }
}

extern "C" void kernel_launch(void* const* d_in, const int* in_sizes, int n_in,
                              void* d_out, int out_size) {
    const float* in = (const float*)d_in[0];
    float* out = (float*)d_out;
    dim3 block(256);
    dim3 grid((HW + 255) / 256);
    rotation_kernel<<<grid, block>>>(in, out);
}

// round 2
// speedup vs baseline: 1.0930x; 1.0930x over previous
#include <cuda_runtime.h>

// Rotation by 15 deg, bilinear, border constant 0, via smem tiling.
// Input/Output: (32, 3, 512, 512) fp32.
//
// Block = 32x32 dst tile x 6 planes. Src bbox for a 32x32 tile rotated 15deg
// is <= 40x40 (incl. bilinear +1); we use 42x42 with +/-1 margin for fp wobble.
// Tile loaded coalesced with zero-fill for out-of-image (matches reference's
// validity-masked weights: invalid tap contributes 0). Taps then read from
// smem: 4 conflict-free LDS + 3 FMA per output. Tap offsets/weights are
// plane-invariant, computed once per thread.

#define H 512
#define W 512
#define HW (H * W)
#define NPLANES 96

#define TW 32          // dst tile width
#define TH 32          // dst tile height
#define SW 42          // src tile width  (40 needed + 2 margin)
#define SH 42          // src tile height
#define PITCH 43       // odd pitch -> conflict-free LDS
#define PP 6           // planes per block
#define PGROUPS (NPLANES / PP)

#define COS_A 0.96592582628906829f
#define SIN_A 0.25881904510252074f

__global__ __launch_bounds__(256)
void rotation_tiled_kernel(const float* __restrict__ in, float* __restrict__ out) {
    __shared__ float tile[SH * PITCH];   // 42*43*4 = 7224 B

    const int tid  = threadIdx.x;
    const int lane = tid & 31;
    const int wid  = tid >> 5;

    const int tx0 = blockIdx.x * TW;
    const int ty0 = blockIdx.y * TH;
    const int p0  = blockIdx.z * PP;

    // Src bounding box for this dst tile.
    // xs = a*(x-256) - b*(y-256) + 256  -> min at (tx0, ty0+31)
    // ys = b*(x-256) + a*(y-256) + 256  -> min at (tx0, ty0)
    const float xs_min = COS_A * ((float)tx0 - 256.0f)
                       - SIN_A * ((float)(ty0 + TH - 1) - 256.0f) + 256.0f;
    const float ys_min = SIN_A * ((float)tx0 - 256.0f)
                       + COS_A * ((float)ty0 - 256.0f) + 256.0f;
    const int gx0 = (int)floorf(xs_min) - 1;   // -1 margin for fp wobble
    const int gy0 = (int)floorf(ys_min) - 1;

    // Per-thread tap setup for 4 outputs (plane-invariant).
    int   offs[4];
    int   ooff[4];
    float wxv[4], wyv[4];
    #pragma unroll
    for (int k = 0; k < 4; k++) {
        const int x = tx0 + lane;
        const int y = ty0 + wid + 8 * k;
        const float xf = (float)x - 256.0f;
        const float yf = (float)y - 256.0f;
        const float xs = COS_A * xf - SIN_A * yf + 256.0f;
        const float ys = SIN_A * xf + COS_A * yf + 256.0f;
        const float x0f = floorf(xs);
        const float y0f = floorf(ys);
        wxv[k] = xs - x0f;
        wyv[k] = ys - y0f;
        const int lx = (int)x0f - gx0;   // in [0, SW-2]
        const int ly = (int)y0f - gy0;   // in [0, SH-2]
        offs[k] = ly * PITCH + lx;
        ooff[k] = y * W + x;
    }

    for (int p = 0; p < PP; p++) {
        const float* __restrict__ src = in  + (long)(p0 + p) * HW;
        float*       __restrict__ dst = out + (long)(p0 + p) * HW;

        // Cooperative coalesced tile load with zero-fill outside the image.
        #pragma unroll
        for (int i = tid; i < SH * SW; i += 256) {
            const int r  = i / SW;
            const int c  = i - r * SW;
            const int gy = gy0 + r;
            const int gx = gx0 + c;
            float v = 0.0f;
            if ((unsigned)gy < (unsigned)H && (unsigned)gx < (unsigned)W)
                v = __ldg(src + gy * W + gx);
            tile[r * PITCH + c] = v;
        }
        __syncthreads();

        #pragma unroll
        for (int k = 0; k < 4; k++) {
            const float* t = tile + offs[k];
            const float v00 = t[0];
            const float v01 = t[1];
            const float v10 = t[PITCH];
            const float v11 = t[PITCH + 1];
            const float top = fmaf(wxv[k], v01 - v00, v00);
            const float bot = fmaf(wxv[k], v11 - v10, v10);
            dst[ooff[k]] = fmaf(wyv[k], bot - top, top);
        }
        __syncthreads();   // protect tile before next plane's load
    }
}

extern "C" void kernel_launch(void* const* d_in, const int* in_sizes, int n_in,
                              void* d_out, int out_size) {
    const float* in = (const float*)d_in[0];
    float* out = (float*)d_out;
    dim3 block(256);
    dim3 grid(W / TW, H / TH, PGROUPS);   // 16 x 16 x 16 = 4096 blocks
    rotation_tiled_kernel<<<grid, block>>>(in, out);
}

// round 3
// speedup vs baseline: 1.7003x; 1.5556x over previous
#include <cuda_runtime.h>
#include <cstdint>

// Rotation 15deg bilinear, border 0. (32,3,512,512) fp32.
// 32x32 dst tile per block, 6 planes/block, double-buffered cp.async tile
// prefetch (16B zfill copies), bilinear from smem (4 LDS + 3 FMA / output).

#define H 512
#define W 512
#define HW (H * W)
#define NPLANES 96

#define TW 32
#define TH 32
#define SW 48            // src tile width in floats (needed <=45 after align-down)
#define SWV 12           // float4s per row
#define SH 42            // src tile height
#define PITCH 48         // floats; rows 16B-aligned for STS.128
#define CELLS_V (SH * SWV)   // 504 float4 copies per tile
#define PP 6
#define PGROUPS (NPLANES / PP)

#define COS_A 0.96592582628906829f
#define SIN_A 0.25881904510252074f

__device__ __forceinline__ uint32_t smem_u32(const void* p) {
    return (uint32_t)__cvta_generic_to_shared(p);
}

__device__ __forceinline__ void cp_async16_zfill(uint32_t saddr, const void* gptr, bool pred) {
    int src_sz = pred ? 16 : 0;
    asm volatile("cp.async.cg.shared.global [%0], [%1], 16, %2;\n"
                 :: "r"(saddr), "l"(gptr), "r"(src_sz));
}
__device__ __forceinline__ void cp_async_commit() {
    asm volatile("cp.async.commit_group;\n" ::: "memory");
}
template <int N>
__device__ __forceinline__ void cp_async_wait() {
    asm volatile("cp.async.wait_group %0;\n" :: "n"(N) : "memory");
}

__global__ __launch_bounds__(256)
void rotation_tiled_kernel(const float* __restrict__ in, float* __restrict__ out) {
    __shared__ float tile[2][SH * PITCH];   // 2 * 8064 B

    const int tid  = threadIdx.x;
    const int lane = tid & 31;
    const int wid  = tid >> 5;

    const int tx0 = blockIdx.x * TW;
    const int ty0 = blockIdx.y * TH;
    const int p0  = blockIdx.z * PP;

    // Src bbox. xs min at (tx0, ty0+31); ys min at (tx0, ty0).
    const float xs_min = COS_A * ((float)tx0 - 256.0f)
                       - SIN_A * ((float)(ty0 + TH - 1) - 256.0f) + 256.0f;
    const float ys_min = SIN_A * ((float)tx0 - 256.0f)
                       + COS_A * ((float)ty0 - 256.0f) + 256.0f;
    const int gx0 = ((int)floorf(xs_min) - 1) & ~3;   // align down to float4
    const int gy0 = (int)floorf(ys_min) - 1;

    // Per-thread copy descriptors (plane-invariant): 2 iterations cover 504 vecs.
    uint32_t cp_saddr[2];
    const float* cp_gbase[2];
    bool cp_pred[2];
    bool cp_do[2];
    #pragma unroll
    for (int it = 0; it < 2; it++) {
        int i = tid + it * 256;
        cp_do[it] = (i < CELLS_V);
        int r = i / SWV;
        int c = i - r * SWV;
        if (!cp_do[it]) { r = 0; c = 0; }
        int gy = gy0 + r;
        int gx = gx0 + 4 * c;
        bool valid = ((unsigned)gy < (unsigned)H) & ((unsigned)gx < (unsigned)W);
        int gyc = min(max(gy, 0), H - 1);
        int gxc = valid ? gx : 0;
        cp_saddr[it] = smem_u32(&tile[0][r * PITCH + 4 * c]);
        cp_gbase[it] = in + gyc * W + gxc;   // plane offset added per plane
        cp_pred[it]  = valid;
    }
    const uint32_t bufstride = (uint32_t)(SH * PITCH * sizeof(float));

    // Per-thread tap setup (plane-invariant).
    int   offs[4];
    int   ooff[4];
    float wxv[4], wyv[4];
    #pragma unroll
    for (int k = 0; k < 4; k++) {
        const int x = tx0 + lane;
        const int y = ty0 + wid + 8 * k;
        const float xf = (float)x - 256.0f;
        const float yf = (float)y - 256.0f;
        const float xs = COS_A * xf - SIN_A * yf + 256.0f;
        const float ys = SIN_A * xf + COS_A * yf + 256.0f;
        const float x0f = floorf(xs);
        const float y0f = floorf(ys);
        wxv[k] = xs - x0f;
        wyv[k] = ys - y0f;
        const int lx = (int)x0f - gx0;
        const int ly = (int)y0f - gy0;
        offs[k] = ly * PITCH + lx;
        ooff[k] = y * W + x;
    }

    // Prefetch plane 0 into buffer 0.
    {
        const long pbase = (long)p0 * HW;
        #pragma unroll
        for (int it = 0; it < 2; it++)
            if (cp_do[it])
                cp_async16_zfill(cp_saddr[it], cp_gbase[it] + pbase, cp_pred[it]);
        cp_async_commit();
    }

    #pragma unroll
    for (int p = 0; p < PP; p++) {
        // Prefetch next plane into the other buffer.
        if (p + 1 < PP) {
            const long pbase = (long)(p0 + p + 1) * HW;
            const uint32_t soff = ((p + 1) & 1) * bufstride;
            #pragma unroll
            for (int it = 0; it < 2; it++)
                if (cp_do[it])
                    cp_async16_zfill(cp_saddr[it] + soff, cp_gbase[it] + pbase, cp_pred[it]);
            cp_async_commit();
            cp_async_wait<1>();   // plane p's group complete
        } else {
            cp_async_wait<0>();
        }
        __syncthreads();

        const float* __restrict__ buf = tile[p & 1];
        float* __restrict__ dst = out + (long)(p0 + p) * HW;

        #pragma unroll
        for (int k = 0; k < 4; k++) {
            const float* t = buf + offs[k];
            const float v00 = t[0];
            const float v01 = t[1];
            const float v10 = t[PITCH];
            const float v11 = t[PITCH + 1];
            const float top = fmaf(wxv[k], v01 - v00, v00);
            const float bot = fmaf(wxv[k], v11 - v10, v10);
            dst[ooff[k]] = fmaf(wyv[k], bot - top, top);
        }
        __syncthreads();   // buf[p&1] reused by prefetch(p+2) next iteration
    }
}

extern "C" void kernel_launch(void* const* d_in, const int* in_sizes, int n_in,
                              void* d_out, int out_size) {
    const float* in = (const float*)d_in[0];
    float* out = (float*)d_out;
    dim3 block(256);
    dim3 grid(W / TW, H / TH, PGROUPS);   // 16 x 16 x 16
    rotation_tiled_kernel<<<grid, block>>>(in, out);
}

// round 4
// speedup vs baseline: 1.9796x; 1.1643x over previous
#include <cuda_runtime.h>
#include <cuda.h>
#include <cstdint>

// Rotation 15deg bilinear, border 0. (32,3,512,512) fp32.
// 32x32 dst tile per block, 6 planes/block. Src tile (48x42) fetched with 3D
// TMA tile loads (native OOB zero-fill), double-buffered via mbarriers.
// Bilinear from smem: 4 conflict-free LDS + 3 FMA per output.

#define H 512
#define W 512
#define HW (H * W)
#define NPLANES 96

#define TW 32
#define TH 32
#define SW 48            // TMA box width (floats); needed <=45 after align-down
#define SH 42            // TMA box height
#define PITCH SW         // TMA packs rows contiguously at box-width pitch
#define TILE_BYTES (SW * SH * 4)   // 8064
#define PP 6
#define PGROUPS (NPLANES / PP)

#define COS_A 0.96592582628906829f
#define SIN_A 0.25881904510252074f

__device__ __forceinline__ uint32_t smem_u32(const void* p) {
    return (uint32_t)__cvta_generic_to_shared(p);
}

__device__ __forceinline__ void mbar_init(uint32_t mbar, uint32_t count) {
    asm volatile("mbarrier.init.shared.b64 [%0], %1;" :: "r"(mbar), "r"(count) : "memory");
}
__device__ __forceinline__ void mbar_expect_tx(uint32_t mbar, uint32_t bytes) {
    asm volatile("mbarrier.arrive.expect_tx.shared.b64 _, [%0], %1;" :: "r"(mbar), "r"(bytes) : "memory");
}
__device__ __forceinline__ void mbar_wait(uint32_t mbar, uint32_t parity) {
    asm volatile(
        "{\n\t"
        ".reg .pred P;\n\t"
        "WAIT_LOOP_%=:\n\t"
        "mbarrier.try_wait.parity.acquire.cta.shared::cta.b64 P, [%0], %1, 0x989680;\n\t"
        "@P bra.uni WAIT_DONE_%=;\n\t"
        "bra.uni WAIT_LOOP_%=;\n\t"
        "WAIT_DONE_%=:\n\t"
        "}"
        :: "r"(mbar), "r"(parity) : "memory");
}
__device__ __forceinline__ void tma_load_3d(uint32_t sdst, const CUtensorMap* tmap,
                                            int cx, int cy, int cz, uint32_t mbar) {
    asm volatile(
        "cp.async.bulk.tensor.3d.shared::cta.global.tile.mbarrier::complete_tx::bytes "
        "[%0], [%1, {%2, %3, %4}], [%5];"
        :: "r"(sdst), "l"(tmap), "r"(cx), "r"(cy), "r"(cz), "r"(mbar) : "memory");
}

__global__ __launch_bounds__(256)
void rotation_tma_kernel(const __grid_constant__ CUtensorMap tmap,
                         float* __restrict__ out) {
    __shared__ __align__(128) float tile[2][SH * PITCH];
    __shared__ __align__(8) unsigned long long mbar_s[2];

    const int tid  = threadIdx.x;
    const int lane = tid & 31;
    const int wid  = tid >> 5;

    const int tx0 = blockIdx.x * TW;
    const int ty0 = blockIdx.y * TH;
    const int p0  = blockIdx.z * PP;

    // Src bbox. xs min at (tx0, ty0+31); ys min at (tx0, ty0).
    const float xs_min = COS_A * ((float)tx0 - 256.0f)
                       - SIN_A * ((float)(ty0 + TH - 1) - 256.0f) + 256.0f;
    const float ys_min = SIN_A * ((float)tx0 - 256.0f)
                       + COS_A * ((float)ty0 - 256.0f) + 256.0f;
    const int gx0 = ((int)floorf(xs_min) - 1) & ~3;   // 16B aligned
    const int gy0 = (int)floorf(ys_min) - 1;

    const uint32_t mb0 = smem_u32(&mbar_s[0]);
    const uint32_t mb1 = smem_u32(&mbar_s[1]);
    const uint32_t sbuf0 = smem_u32(&tile[0][0]);
    const uint32_t sbuf1 = smem_u32(&tile[1][0]);

    if (tid == 0) {
        mbar_init(mb0, 1);
        mbar_init(mb1, 1);
    }
    __syncthreads();

    // Prefetch plane 0 into buffer 0.
    if (tid == 0) {
        mbar_expect_tx(mb0, TILE_BYTES);
        tma_load_3d(sbuf0, &tmap, gx0, gy0, p0, mb0);
    }

    // Per-thread tap setup (plane-invariant).
    int   offs[4];
    int   ooff[4];
    float wxv[4], wyv[4];
    #pragma unroll
    for (int k = 0; k < 4; k++) {
        const int x = tx0 + lane;
        const int y = ty0 + wid + 8 * k;
        const float xf = (float)x - 256.0f;
        const float yf = (float)y - 256.0f;
        const float xs = COS_A * xf - SIN_A * yf + 256.0f;
        const float ys = SIN_A * xf + COS_A * yf + 256.0f;
        const float x0f = floorf(xs);
        const float y0f = floorf(ys);
        wxv[k] = xs - x0f;
        wyv[k] = ys - y0f;
        const int lx = (int)x0f - gx0;
        const int ly = (int)y0f - gy0;
        offs[k] = ly * PITCH + lx;
        ooff[k] = y * W + x;
    }

    #pragma unroll
    for (int p = 0; p < PP; p++) {
        // Prefetch next plane into the other buffer (its previous consumer,
        // plane p-1, finished at the __syncthreads ending the last iteration).
        if (p + 1 < PP && tid == 0) {
            const uint32_t mb = ((p + 1) & 1) ? mb1 : mb0;
            const uint32_t sb = ((p + 1) & 1) ? sbuf1 : sbuf0;
            mbar_expect_tx(mb, TILE_BYTES);
            tma_load_3d(sb, &tmap, gx0, gy0, p0 + p + 1, mb);
        }

        // Wait for plane p's tile.
        mbar_wait((p & 1) ? mb1 : mb0, (p >> 1) & 1);

        const float* __restrict__ buf = tile[p & 1];
        float* __restrict__ dst = out + (long)(p0 + p) * HW;

        #pragma unroll
        for (int k = 0; k < 4; k++) {
            const float* t = buf + offs[k];
            const float v00 = t[0];
            const float v01 = t[1];
            const float v10 = t[PITCH];
            const float v11 = t[PITCH + 1];
            const float top = fmaf(wxv[k], v01 - v00, v00);
            const float bot = fmaf(wxv[k], v11 - v10, v10);
            dst[ooff[k]] = fmaf(wyv[k], bot - top, top);
        }
        __syncthreads();   // all reads of buf[p&1] done before it is refilled
    }
}

// ---- host side ----

typedef CUresult (*EncodeTiledFn)(
    CUtensorMap*, CUtensorMapDataType, cuuint32_t, void*,
    const cuuint64_t*, const cuuint64_t*, const cuuint32_t*, const cuuint32_t*,
    CUtensorMapInterleave, CUtensorMapSwizzle, CUtensorMapL2promotion,
    CUtensorMapFloatOOBfill);

extern "C" void kernel_launch(void* const* d_in, const int* in_sizes, int n_in,
                              void* d_out, int out_size) {
    float* in = (float*)d_in[0];
    float* out = (float*)d_out;

    void* fn = nullptr;
    cudaDriverEntryPointQueryResult qres;
    cudaGetDriverEntryPoint("cuTensorMapEncodeTiled", &fn, cudaEnableDefault, &qres);
    EncodeTiledFn encode = (EncodeTiledFn)fn;

    CUtensorMap tmap;
    cuuint64_t gdims[3]    = {W, H, NPLANES};
    cuuint64_t gstrides[2] = {W * sizeof(float), (cuuint64_t)HW * sizeof(float)};
    cuuint32_t box[3]      = {SW, SH, 1};
    cuuint32_t estrides[3] = {1, 1, 1};
    encode(&tmap, CU_TENSOR_MAP_DATA_TYPE_FLOAT32, 3, in,
           gdims, gstrides, box, estrides,
           CU_TENSOR_MAP_INTERLEAVE_NONE, CU_TENSOR_MAP_SWIZZLE_NONE,
           CU_TENSOR_MAP_L2_PROMOTION_L2_128B, CU_TENSOR_MAP_FLOAT_OOB_FILL_NONE);

    dim3 block(256);
    dim3 grid(W / TW, H / TH, PGROUPS);   // 16 x 16 x 16
    rotation_tma_kernel<<<grid, block>>>(tmap, out);
}

// round 5
// speedup vs baseline: 1.9880x; 1.0043x over previous
#include <cuda_runtime.h>
#include <cuda.h>
#include <cstdint>

// Rotation 15deg bilinear, border 0. (32,3,512,512) fp32.
// 32x32 dst tile per block, 12 planes/block. Src tile (48x42) fetched by 3D
// TMA (native OOB zero-fill) into a 4-deep smem ring with full/empty
// mbarriers; no __syncthreads in the steady-state loop.
// Bilinear from smem: 4 conflict-free LDS + 3 FMA per output.

#define H 512
#define W 512
#define HW (H * W)
#define NPLANES 96

#define TW 32
#define TH 32
#define SW 48            // TMA box width (floats); 192B row pitch (16B mult)
#define SH 42            // TMA box height
#define PITCH SW
#define TILE_BYTES (SW * SH * 4)   // 8064
#define NSTAGES 4
#define PP 12
#define PGROUPS (NPLANES / PP)     // 8

#define COS_A 0.96592582628906829f
#define SIN_A 0.25881904510252074f

__device__ __forceinline__ uint32_t smem_u32(const void* p) {
    return (uint32_t)__cvta_generic_to_shared(p);
}
__device__ __forceinline__ void mbar_init(uint32_t mbar, uint32_t count) {
    asm volatile("mbarrier.init.shared.b64 [%0], %1;" :: "r"(mbar), "r"(count) : "memory");
}
__device__ __forceinline__ void mbar_expect_tx(uint32_t mbar, uint32_t bytes) {
    asm volatile("mbarrier.arrive.expect_tx.shared.b64 _, [%0], %1;" :: "r"(mbar), "r"(bytes) : "memory");
}
__device__ __forceinline__ void mbar_arrive(uint32_t mbar) {
    asm volatile("mbarrier.arrive.shared.b64 _, [%0];" :: "r"(mbar) : "memory");
}
__device__ __forceinline__ void mbar_wait_acq(uint32_t mbar, uint32_t parity) {
    asm volatile(
        "{\n\t.reg .pred P;\n\t"
        "WL_%=:\n\t"
        "mbarrier.try_wait.parity.acquire.cta.shared::cta.b64 P, [%0], %1, 0x989680;\n\t"
        "@P bra.uni WD_%=;\n\t"
        "bra.uni WL_%=;\n\t"
        "WD_%=:\n\t}"
        :: "r"(mbar), "r"(parity) : "memory");
}
__device__ __forceinline__ void mbar_wait_rlx(uint32_t mbar, uint32_t parity) {
    asm volatile(
        "{\n\t.reg .pred P;\n\t"
        "WL_%=:\n\t"
        "mbarrier.try_wait.parity.relaxed.cta.shared::cta.b64 P, [%0], %1, 0x989680;\n\t"
        "@P bra.uni WD_%=;\n\t"
        "bra.uni WL_%=;\n\t"
        "WD_%=:\n\t}"
        :: "r"(mbar), "r"(parity) : "memory");
}
__device__ __forceinline__ void tma_load_3d(uint32_t sdst, const CUtensorMap* tmap,
                                            int cx, int cy, int cz, uint32_t mbar) {
    asm volatile(
        "cp.async.bulk.tensor.3d.shared::cta.global.tile.mbarrier::complete_tx::bytes "
        "[%0], [%1, {%2, %3, %4}], [%5];"
        :: "r"(sdst), "l"(tmap), "r"(cx), "r"(cy), "r"(cz), "r"(mbar) : "memory");
}

__global__ __launch_bounds__(256)
void rotation_tma_kernel(const __grid_constant__ CUtensorMap tmap,
                         float* __restrict__ out) {
    __shared__ __align__(128) float tile[NSTAGES][SH * PITCH];   // 32256 B
    __shared__ __align__(8) unsigned long long mbar_full[NSTAGES];
    __shared__ __align__(8) unsigned long long mbar_empty[NSTAGES];

    const int tid  = threadIdx.x;
    const int lane = tid & 31;
    const int wid  = tid >> 5;

    const int tx0 = blockIdx.x * TW;
    const int ty0 = blockIdx.y * TH;
    const int p0  = blockIdx.z * PP;

    // Src bbox. xs min at (tx0, ty0+31); ys min at (tx0, ty0).
    const float xs_min = COS_A * ((float)tx0 - 256.0f)
                       - SIN_A * ((float)(ty0 + TH - 1) - 256.0f) + 256.0f;
    const float ys_min = SIN_A * ((float)tx0 - 256.0f)
                       + COS_A * ((float)ty0 - 256.0f) + 256.0f;
    const int gx0 = ((int)floorf(xs_min) - 1) & ~3;
    const int gy0 = (int)floorf(ys_min) - 1;

    uint32_t mbf[NSTAGES], mbe[NSTAGES], sbuf[NSTAGES];
    #pragma unroll
    for (int s = 0; s < NSTAGES; s++) {
        mbf[s]  = smem_u32(&mbar_full[s]);
        mbe[s]  = smem_u32(&mbar_empty[s]);
        sbuf[s] = smem_u32(&tile[s][0]);
    }

    if (tid == 0) {
        #pragma unroll
        for (int s = 0; s < NSTAGES; s++) {
            mbar_init(mbf[s], 1);
            mbar_init(mbe[s], 256);
        }
    }
    __syncthreads();

    // Prologue: fill first 3 stages.
    if (tid == 0) {
        #pragma unroll
        for (int q = 0; q < 3; q++) {
            mbar_expect_tx(mbf[q], TILE_BYTES);
            tma_load_3d(sbuf[q], &tmap, gx0, gy0, p0 + q, mbf[q]);
        }
    }

    // Per-thread tap setup (plane-invariant).
    int   offs[4];
    float wxv[4], wyv[4];
    #pragma unroll
    for (int k = 0; k < 4; k++) {
        const int x = tx0 + lane;
        const int y = ty0 + wid + 8 * k;
        const float xf = (float)x - 256.0f;
        const float yf = (float)y - 256.0f;
        const float xs = COS_A * xf - SIN_A * yf + 256.0f;
        const float ys = SIN_A * xf + COS_A * yf + 256.0f;
        const float x0f = floorf(xs);
        const float y0f = floorf(ys);
        wxv[k] = xs - x0f;
        wyv[k] = ys - y0f;
        offs[k] = ((int)y0f - gy0) * PITCH + ((int)x0f - gx0);
    }
    const int obase = (ty0 + wid) * W + (tx0 + lane);
    float* __restrict__ dst0 = out + (long)p0 * HW + obase;

    #pragma unroll
    for (int p = 0; p < PP; p++) {
        // Producer: prefetch plane p+3 into stage (p+3)&3 (not the stage
        // being consumed now, so no self-wait deadlock).
        if (tid == 0 && p + 3 < PP) {
            const int q = p + 3;
            const int s = q & 3;
            if (q >= NSTAGES)
                mbar_wait_rlx(mbe[s], ((q >> 2) + 1) & 1);   // prior consumer done
            mbar_expect_tx(mbf[s], TILE_BYTES);
            tma_load_3d(sbuf[s], &tmap, gx0, gy0, p0 + q, mbf[s]);
        }

        const int s = p & 3;
        mbar_wait_acq(mbf[s], (p >> 2) & 1);

        const float* __restrict__ buf = tile[s];
        float* __restrict__ dst = dst0 + (long)p * HW;

        #pragma unroll
        for (int k = 0; k < 4; k++) {
            const float* t = buf + offs[k];
            const float v00 = t[0];
            const float v01 = t[1];
            const float v10 = t[PITCH];
            const float v11 = t[PITCH + 1];
            const float top = fmaf(wxv[k], v01 - v00, v00);
            const float bot = fmaf(wxv[k], v11 - v10, v10);
            dst[k * (8 * W)] = fmaf(wyv[k], bot - top, top);
        }
        mbar_arrive(mbe[s]);   // release: LDS reads done, stage reusable
    }
}

// ---- host side ----

typedef CUresult (*EncodeTiledFn)(
    CUtensorMap*, CUtensorMapDataType, cuuint32_t, void*,
    const cuuint64_t*, const cuuint64_t*, const cuuint32_t*, const cuuint32_t*,
    CUtensorMapInterleave, CUtensorMapSwizzle, CUtensorMapL2promotion,
    CUtensorMapFloatOOBfill);

extern "C" void kernel_launch(void* const* d_in, const int* in_sizes, int n_in,
                              void* d_out, int out_size) {
    float* in = (float*)d_in[0];
    float* out = (float*)d_out;

    void* fn = nullptr;
    cudaDriverEntryPointQueryResult qres;
    cudaGetDriverEntryPoint("cuTensorMapEncodeTiled", &fn, cudaEnableDefault, &qres);
    EncodeTiledFn encode = (EncodeTiledFn)fn;

    CUtensorMap tmap;
    cuuint64_t gdims[3]    = {W, H, NPLANES};
    cuuint64_t gstrides[2] = {W * sizeof(float), (cuuint64_t)HW * sizeof(float)};
    cuuint32_t box[3]      = {SW, SH, 1};
    cuuint32_t estrides[3] = {1, 1, 1};
    encode(&tmap, CU_TENSOR_MAP_DATA_TYPE_FLOAT32, 3, in,
           gdims, gstrides, box, estrides,
           CU_TENSOR_MAP_INTERLEAVE_NONE, CU_TENSOR_MAP_SWIZZLE_NONE,
           CU_TENSOR_MAP_L2_PROMOTION_L2_128B, CU_TENSOR_MAP_FLOAT_OOB_FILL_NONE);

    dim3 block(256);
    dim3 grid(W / TW, H / TH, PGROUPS);   // 16 x 16 x 8 = 2048
    rotation_tma_kernel<<<grid, block>>>(tmap, out);
}